// round 11
// baseline (speedup 1.0000x reference)
#include <cuda_runtime.h>
#include <stdint.h>

#define N_NODES 50000
#define DIM     128        // D == O == 128
#define E_MAX   800016     // per-relation edge capacity (problem fixes E=800000)
#define A_PAD   132        // shared A row stride in words (conflict-free pairs)

#define NROWS2  (2 * N_NODES)                      // flattened rows (2 relations)
#define SCAN_B  256
#define NBLK    ((NROWS2 + SCAN_B - 1) / SCAN_B)   // 391

// ---------------------------------------------------------------------------
// Static scratch (no cudaMalloc allowed). g_cnt / g_flag / g_ticket are ZERO
// at entry to every kernel_launch call: zero-initialized statics on the first
// call, and spmm_csr_kernel (which does not read them) re-zeros them on every
// call, restoring the invariant for the next graph replay.
// ---------------------------------------------------------------------------
__device__ float g_x1[N_NODES * DIM];        // in @ W1   (25.6 MB)
__device__ float g_x2[N_NODES * DIM];        // in @ W2   (25.6 MB)

__device__ int  g_cnt[NROWS2];               // per-row edge counts
__device__ int  g_off[NROWS2 + 1];           // CSR row pointers
__device__ int  g_pos[NROWS2];               // scatter cursors
__device__ int2 g_edge[2 * E_MAX];           // packed (col, val-bits)

// Decoupled-lookback scan state.
__device__ int  g_ticket;                    // block-id ticket counter
__device__ int  g_agg[NBLK];                 // per-block aggregate   (flag==1)
__device__ int  g_incl[NBLK];                // per-block incl prefix (flag==2)
__device__ int  g_flag[NBLK];                // 0=none, 1=agg, 2=inclusive

__device__ __forceinline__ uint32_t f2tf32(float f) {
    uint32_t r;
    asm("cvt.rna.tf32.f32 %0, %1;" : "=r"(r) : "f"(f));
    return r;
}

// ---------------------------------------------------------------------------
// Histogram over BOTH relations: thread owns one 4-edge vector group.
// Requires g_cnt == 0 (invariant).
// ---------------------------------------------------------------------------
__global__ void __launch_bounds__(256)
hist4_kernel(const int* __restrict__ r1, const int* __restrict__ r2,
             int E1, int E2)
{
    const int V1 = (E1 + 3) >> 2;
    const int V2 = (E2 + 3) >> 2;
    int v = blockIdx.x * blockDim.x + threadIdx.x;
    const int* rows; int E, rowbase;
    if (v < V1)            { rows = r1; E = E1; rowbase = 0; }
    else if (v < V1 + V2)  { rows = r2; E = E2; rowbase = N_NODES; v -= V1; }
    else return;

    const int i = v * 4;
    if (i + 3 < E) {
        const int4 r = __ldg(reinterpret_cast<const int4*>(rows) + v);
        atomicAdd(&g_cnt[rowbase + r.x], 1);
        atomicAdd(&g_cnt[rowbase + r.y], 1);
        atomicAdd(&g_cnt[rowbase + r.z], 1);
        atomicAdd(&g_cnt[rowbase + r.w], 1);
    } else {
        for (int k = i; k < E; ++k)
            atomicAdd(&g_cnt[rowbase + __ldg(rows + k)], 1);
    }
}

// ---------------------------------------------------------------------------
// Single-pass exclusive scan, decoupled lookback, WARP-PARALLEL window.
// Requires g_ticket == 0 and g_flag[] == 0 (invariant).
// ---------------------------------------------------------------------------
__global__ void __launch_bounds__(SCAN_B)
scan_lookback_kernel()
{
    __shared__ int sh[SCAN_B];
    __shared__ int s_bid;
    __shared__ int s_base;

    const int t = threadIdx.x;
    if (t == 0) s_bid = atomicAdd(&g_ticket, 1);
    __syncthreads();
    const int bid = s_bid;

    const int i = bid * SCAN_B + t;
    const int v = (i < NROWS2) ? g_cnt[i] : 0;
    sh[t] = v;
    __syncthreads();
    #pragma unroll
    for (int d = 1; d < SCAN_B; d <<= 1) {
        int u = (t >= d) ? sh[t - d] : 0;
        __syncthreads();
        sh[t] += u;
        __syncthreads();
    }
    const int total = sh[SCAN_B - 1];

    if (t < 32) {                               // warp 0: publish + lookback
        if (bid > 0) {
            if (t == 0) {
                g_agg[bid] = total;
                __threadfence();
                atomicExch(&g_flag[bid], 1);
            }
            __syncwarp();

            int run = 0;
            int wend = bid;                     // exclusive window end
            for (;;) {
                const int j = wend - 32 + t;
                int f, a;
                if (j >= 0) {
                    do { f = *(volatile int*)&g_flag[j]; } while (f == 0);
                    __threadfence();            // acquire before value read
                    a = (f == 2) ? *(volatile int*)&g_incl[j]
                                 : *(volatile int*)&g_agg[j];
                } else { f = 2; a = 0; }        // virtual block -1: incl == 0
                const unsigned m = __ballot_sync(0xffffffffu, f == 2);
                if (m) {
                    const int lead = 31 - __clz(m);
                    int c = (t >= lead) ? a : 0;
                    #pragma unroll
                    for (int o = 16; o; o >>= 1)
                        c += __shfl_down_sync(0xffffffffu, c, o);
                    run += __shfl_sync(0xffffffffu, c, 0);
                    break;
                } else {
                    int c = a;
                    #pragma unroll
                    for (int o = 16; o; o >>= 1)
                        c += __shfl_down_sync(0xffffffffu, c, o);
                    run += __shfl_sync(0xffffffffu, c, 0);
                    wend -= 32;
                }
            }

            if (t == 0) {
                g_incl[bid] = run + total;
                __threadfence();
                atomicExch(&g_flag[bid], 2);
                s_base = run;
            }
        } else if (t == 0) {
            g_incl[0] = total;
            __threadfence();
            atomicExch(&g_flag[0], 2);
            s_base = 0;
        }
    }
    __syncthreads();

    const int base = s_base;
    if (i < NROWS2) {
        const int o = base + sh[t] - v;                // exclusive prefix
        g_off[i] = o;
        g_pos[i] = o;
    }
    if (bid == NBLK - 1 && t == SCAN_B - 1)
        g_off[NROWS2] = base + total;                  // grand total sentinel
}

// ---------------------------------------------------------------------------
// Scatter over BOTH relations (standalone: lean regs, high occupancy).
// ---------------------------------------------------------------------------
__global__ void __launch_bounds__(256)
scatter4_kernel(const int* __restrict__ r1, const int* __restrict__ c1,
                const float* __restrict__ v1,
                const int* __restrict__ r2, const int* __restrict__ c2,
                const float* __restrict__ v2,
                int E1, int E2)
{
    const int V1 = (E1 + 3) >> 2;
    const int V2 = (E2 + 3) >> 2;
    int v = blockIdx.x * blockDim.x + threadIdx.x;
    const int* rows; const int* cols; const float* vals; int E, rowbase;
    if (v < V1)           { rows = r1; cols = c1; vals = v1; E = E1; rowbase = 0; }
    else if (v < V1 + V2) { rows = r2; cols = c2; vals = v2; E = E2; rowbase = N_NODES; v -= V1; }
    else return;

    const int i = v * 4;
    if (i + 3 < E) {
        const int4   r = __ldg(reinterpret_cast<const int4*>(rows) + v);
        const int4   c = __ldg(reinterpret_cast<const int4*>(cols) + v);
        const float4 w = __ldg(reinterpret_cast<const float4*>(vals) + v);
        const int p0 = atomicAdd(&g_pos[rowbase + r.x], 1);
        const int p1 = atomicAdd(&g_pos[rowbase + r.y], 1);
        const int p2 = atomicAdd(&g_pos[rowbase + r.z], 1);
        const int p3 = atomicAdd(&g_pos[rowbase + r.w], 1);
        g_edge[p0] = make_int2(c.x, __float_as_int(w.x));
        g_edge[p1] = make_int2(c.y, __float_as_int(w.y));
        g_edge[p2] = make_int2(c.z, __float_as_int(w.z));
        g_edge[p3] = make_int2(c.w, __float_as_int(w.w));
    } else {
        for (int k = i; k < E; ++k) {
            const int p = atomicAdd(&g_pos[rowbase + __ldg(rows + k)], 1);
            g_edge[p] = make_int2(__ldg(cols + k), __float_as_int(__ldg(vals + k)));
        }
    }
}

// ---------------------------------------------------------------------------
// Dense projection on tensor cores: x = in @ W per relation (blockIdx.y).
// R10 ILP surgery:
//   * Paired-A smem layout: columns (c, c+4) stored adjacently so each A
//     fragment half is ONE LDS.64 (2 loads/kk instead of 4 scalar loads).
//     Word address = 4r + 2j + {0,1} (mod 32) -> all 32 banks hit once.
//   * Split accumulators (even kk -> accA, odd kk -> accB): MMA dependency
//     chain halves (16 -> 8), 4 independent chains per warp.
// ---------------------------------------------------------------------------
__global__ void __launch_bounds__(256, 2)
gemm_tf32_kernel(const float* __restrict__ in,
                 const float* __restrict__ W1,
                 const float* __restrict__ W2)
{
    __shared__ uint32_t shA[64 * A_PAD];

    const int tid  = threadIdx.x;
    const int warp = tid >> 5;
    const int lane = tid & 31;
    const float* __restrict__ W    = blockIdx.y ? W2   : W1;
    float*       __restrict__ xout = blockIdx.y ? g_x2 : g_x1;

    // B fragments: warp w owns output cols [16w, 16w+16), all 16 K-steps.
    const int col0 = warp * 16;
    uint32_t Bf[2][16][2];
    #pragma unroll
    for (int nt = 0; nt < 2; ++nt) {
        const int n = col0 + nt * 8 + (lane >> 2);
        #pragma unroll
        for (int kk = 0; kk < 16; ++kk) {
            const int k = kk * 8 + (lane & 3);
            Bf[nt][kk][0] = f2tf32(__ldg(W + k * DIM + n));
            Bf[nt][kk][1] = f2tf32(__ldg(W + (k + 4) * DIM + n));
        }
    }

    #pragma unroll
    for (int t = 0; t < 2; ++t) {
        const int row0 = blockIdx.x * 128 + t * 64;

        // Stage A tile (64 x 128) -> paired layout:
        //   shA[r*A_PAD + kk*8 + j*2 + p] = tf32(A[r][kk*8 + j + 4p])
        #pragma unroll
        for (int i = 0; i < 8; ++i) {
            int idx = tid + i * 256;
            int r    = idx >> 5;
            int c4   = idx & 31;              // float4 group: cols 4c4..4c4+3
            int kk   = c4 >> 1;
            int half = c4 & 1;                // p: 0 -> cols 8kk..+3, 1 -> +4..+7
            float4 v = make_float4(0.f, 0.f, 0.f, 0.f);
            if (row0 + r < N_NODES)
                v = __ldg(reinterpret_cast<const float4*>(in + (size_t)(row0 + r) * DIM) + c4);
            uint32_t* s = shA + r * A_PAD + kk * 8 + half;
            s[0] = f2tf32(v.x);               // j = 0
            s[2] = f2tf32(v.y);               // j = 1
            s[4] = f2tf32(v.z);               // j = 2
            s[6] = f2tf32(v.w);               // j = 3
        }
        __syncthreads();

        #pragma unroll
        for (int rt = 0; rt < 4; ++rt) {
            float accA[2][4] = {};            // even kk chain
            float accB[2][4] = {};            // odd  kk chain
            const uint32_t* sA = shA + (rt * 16) * A_PAD;
            const int r = lane >> 2;
            const int jj = (lane & 3) * 2;

            #pragma unroll
            for (int kk = 0; kk < 16; kk += 2) {
                // ---- even step -> accA ----
                {
                    const uint2 lo = *reinterpret_cast<const uint2*>(
                        sA + r * A_PAD + kk * 8 + jj);           // a0 (r,c), a2 (r,c+4)
                    const uint2 hi = *reinterpret_cast<const uint2*>(
                        sA + (r + 8) * A_PAD + kk * 8 + jj);     // a1, a3
                    #pragma unroll
                    for (int nt = 0; nt < 2; ++nt) {
                        asm volatile(
                            "mma.sync.aligned.m16n8k8.row.col.f32.tf32.tf32.f32 "
                            "{%0,%1,%2,%3}, {%4,%5,%6,%7}, {%8,%9}, {%0,%1,%2,%3};"
                            : "+f"(accA[nt][0]), "+f"(accA[nt][1]),
                              "+f"(accA[nt][2]), "+f"(accA[nt][3])
                            : "r"(lo.x), "r"(hi.x), "r"(lo.y), "r"(hi.y),
                              "r"(Bf[nt][kk][0]), "r"(Bf[nt][kk][1]));
                    }
                }
                // ---- odd step -> accB (independent chain) ----
                {
                    const uint2 lo = *reinterpret_cast<const uint2*>(
                        sA + r * A_PAD + (kk + 1) * 8 + jj);
                    const uint2 hi = *reinterpret_cast<const uint2*>(
                        sA + (r + 8) * A_PAD + (kk + 1) * 8 + jj);
                    #pragma unroll
                    for (int nt = 0; nt < 2; ++nt) {
                        asm volatile(
                            "mma.sync.aligned.m16n8k8.row.col.f32.tf32.tf32.f32 "
                            "{%0,%1,%2,%3}, {%4,%5,%6,%7}, {%8,%9}, {%0,%1,%2,%3};"
                            : "+f"(accB[nt][0]), "+f"(accB[nt][1]),
                              "+f"(accB[nt][2]), "+f"(accB[nt][3])
                            : "r"(lo.x), "r"(hi.x), "r"(lo.y), "r"(hi.y),
                              "r"(Bf[nt][kk + 1][0]), "r"(Bf[nt][kk + 1][1]));
                    }
                }
            }

            const int rowa = row0 + rt * 16 + (lane >> 2);
            const int rowb = rowa + 8;
            #pragma unroll
            for (int nt = 0; nt < 2; ++nt) {
                const int c = col0 + nt * 8 + 2 * (lane & 3);
                if (rowa < N_NODES)
                    *reinterpret_cast<float2*>(xout + (size_t)rowa * DIM + c) =
                        make_float2(accA[nt][0] + accB[nt][0],
                                    accA[nt][1] + accB[nt][1]);
                if (rowb < N_NODES)
                    *reinterpret_cast<float2*>(xout + (size_t)rowb * DIM + c) =
                        make_float2(accA[nt][2] + accB[nt][2],
                                    accA[nt][3] + accB[nt][3]);
            }
        }
        __syncthreads();   // shA reused by next tile
    }
}

// ---------------------------------------------------------------------------
// Segmented SpMM, warp-cooperative (unchanged: 62 us, at LTS gather floor).
// Also restores the zero-state invariant.
// ---------------------------------------------------------------------------
__device__ __forceinline__ void row_accum(const float* __restrict__ x,
                                          int s, int e, int lane,
                                          int* __restrict__ shc,
                                          int* __restrict__ shv,
                                          float4& acc)
{
    for (int i = s; i < e; i += 32) {
        const int idx = i + lane;
        if (idx < e) {
            const int2 t = __ldg(&g_edge[idx]);
            shc[lane] = t.x;
            shv[lane] = t.y;
        }
        __syncwarp();
        const int m = min(e - i, 32);
        int j = 0;
        for (; j + 4 <= m; j += 4) {
            const int c0 = shc[j],     c1 = shc[j + 1];
            const int c2 = shc[j + 2], c3 = shc[j + 3];
            const float4 x0 = __ldg(reinterpret_cast<const float4*>(x + (size_t)c0 * DIM) + lane);
            const float4 x1 = __ldg(reinterpret_cast<const float4*>(x + (size_t)c1 * DIM) + lane);
            const float4 x2 = __ldg(reinterpret_cast<const float4*>(x + (size_t)c2 * DIM) + lane);
            const float4 x3 = __ldg(reinterpret_cast<const float4*>(x + (size_t)c3 * DIM) + lane);
            const float v0 = __int_as_float(shv[j]);
            const float v1 = __int_as_float(shv[j + 1]);
            const float v2 = __int_as_float(shv[j + 2]);
            const float v3 = __int_as_float(shv[j + 3]);
            acc.x = fmaf(v0, x0.x, acc.x); acc.y = fmaf(v0, x0.y, acc.y);
            acc.z = fmaf(v0, x0.z, acc.z); acc.w = fmaf(v0, x0.w, acc.w);
            acc.x = fmaf(v1, x1.x, acc.x); acc.y = fmaf(v1, x1.y, acc.y);
            acc.z = fmaf(v1, x1.z, acc.z); acc.w = fmaf(v1, x1.w, acc.w);
            acc.x = fmaf(v2, x2.x, acc.x); acc.y = fmaf(v2, x2.y, acc.y);
            acc.z = fmaf(v2, x2.z, acc.z); acc.w = fmaf(v2, x2.w, acc.w);
            acc.x = fmaf(v3, x3.x, acc.x); acc.y = fmaf(v3, x3.y, acc.y);
            acc.z = fmaf(v3, x3.z, acc.z); acc.w = fmaf(v3, x3.w, acc.w);
        }
        for (; j < m; ++j) {
            const int   c  = shc[j];
            const float v  = __int_as_float(shv[j]);
            const float4 xv = __ldg(reinterpret_cast<const float4*>(x + (size_t)c * DIM) + lane);
            acc.x = fmaf(v, xv.x, acc.x); acc.y = fmaf(v, xv.y, acc.y);
            acc.z = fmaf(v, xv.z, acc.z); acc.w = fmaf(v, xv.w, acc.w);
        }
        __syncwarp();
    }
}

__global__ void __launch_bounds__(256)
spmm_csr_kernel(float* __restrict__ out)
{
    __shared__ int shc[8][32];
    __shared__ int shv[8][32];

    const int warp = threadIdx.x >> 5;
    const int lane = threadIdx.x & 31;
    const int row  = blockIdx.x * 8 + warp;

    // Restore zero-state invariant for the next call (not read here).
    // 6250 blocks x 16 lanes = 100000 = NROWS2 exactly.
    if (warp == 0) {
        const int z = blockIdx.x * 16 + lane;
        if (lane < 16 && z < NROWS2) g_cnt[z] = 0;
    } else if (warp == 1 && lane == 0) {
        if (blockIdx.x < NBLK) g_flag[blockIdx.x] = 0;
        if (blockIdx.x == 0)   g_ticket = 0;
    }

    if (row >= N_NODES) return;

    float4 acc = make_float4(0.f, 0.f, 0.f, 0.f);

    row_accum(g_x1, g_off[row],           g_off[row + 1],
              lane, shc[warp], shv[warp], acc);
    row_accum(g_x2, g_off[N_NODES + row], g_off[N_NODES + row + 1],
              lane, shc[warp], shv[warp], acc);

    acc.x = fmaxf(acc.x, 0.f); acc.y = fmaxf(acc.y, 0.f);
    acc.z = fmaxf(acc.z, 0.f); acc.w = fmaxf(acc.w, 0.f);
    reinterpret_cast<float4*>(out + (size_t)row * DIM)[lane] = acc;
}

// ---------------------------------------------------------------------------
// Entry point. Inputs (metadata order):
//   0 inputs[N,128] f32 | 1 adj1_rows i32 | 2 adj1_cols i32 | 3 adj1_vals f32
//   4 adj2_rows i32 | 5 adj2_cols i32 | 6 adj2_vals f32
//   7 weights_1[128,128] f32 | 8 weights_2[128,128] f32
// Output: [N,128] f32.  5 launches total.
// ---------------------------------------------------------------------------
extern "C" void kernel_launch(void* const* d_in, const int* in_sizes, int n_in,
                              void* d_out, int out_size)
{
    const float* in  = (const float*)d_in[0];
    const int*   a1r = (const int*)  d_in[1];
    const int*   a1c = (const int*)  d_in[2];
    const float* a1v = (const float*)d_in[3];
    const int*   a2r = (const int*)  d_in[4];
    const int*   a2c = (const int*)  d_in[5];
    const float* a2v = (const float*)d_in[6];
    const float* W1  = (const float*)d_in[7];
    const float* W2  = (const float*)d_in[8];
    float*       out = (float*)d_out;

    const int E1 = in_sizes[1];
    const int E2 = in_sizes[4];

    const int Vtot = (E1 + 3) / 4 + (E2 + 3) / 4;
    const int eblk = (Vtot + 255) / 256;

    // 1. Histogram (g_cnt zero by invariant).
    hist4_kernel<<<eblk, 256>>>(a1r, a2r, E1, E2);

    // 2. Single-pass scan with WARP-PARALLEL decoupled lookback.
    scan_lookback_kernel<<<NBLK, SCAN_B>>>();

    // 3. Edge scatter into CSR order.
    scatter4_kernel<<<eblk, 256>>>(a1r, a1c, a1v, a2r, a2c, a2v, E1, E2);

    // 4. Tensor-core projections (paired-A LDS.64 + split acc chains).
    dim3 ggrid((N_NODES + 127) / 128, 2);
    gemm_tf32_kernel<<<ggrid, 256>>>(in, W1, W2);

    // 5. Segmented SpMM + fused ReLU + invariant restore.
    spmm_csr_kernel<<<(N_NODES + 7) / 8, 256>>>(out);
}

// round 12
// speedup vs baseline: 1.1579x; 1.1579x over previous
#include <cuda_runtime.h>
#include <stdint.h>

#define N_NODES 50000
#define DIM     128        // D == O == 128
#define E_MAX   800016     // per-relation edge capacity (problem fixes E=800000)
#define A_PAD   132        // shared A row stride (bank-conflict-free scalar frags)

#define NROWS2  (2 * N_NODES)                      // flattened rows (2 relations)
#define SCAN_B  256
#define NBLK    ((NROWS2 + SCAN_B - 1) / SCAN_B)   // 391

// ---------------------------------------------------------------------------
// Static scratch (no cudaMalloc allowed). g_cnt is ZERO at entry to every
// kernel_launch call: zero-initialized static on the first call, and
// spmm_csr_kernel (which does not read it) re-zeros it on every call.
// ---------------------------------------------------------------------------
__device__ float g_x1[N_NODES * DIM];        // in @ W1   (25.6 MB)
__device__ float g_x2[N_NODES * DIM];        // in @ W2   (25.6 MB)

__device__ int  g_cnt[NROWS2];               // per-row edge counts
__device__ int  g_off[NROWS2 + 1];           // CSR row pointers
__device__ int  g_pos[NROWS2];               // scatter cursors
__device__ int  g_bsum[NBLK];                // scanA block sums
__device__ int2 g_edge[2 * E_MAX];           // packed (col, val-bits)

__device__ __forceinline__ uint32_t f2tf32(float f) {
    uint32_t r;
    asm("cvt.rna.tf32.f32 %0, %1;" : "=r"(r) : "f"(f));
    return r;
}

// ---------------------------------------------------------------------------
// Histogram over BOTH relations: thread owns one 4-edge vector group.
// Requires g_cnt == 0 (invariant).
// ---------------------------------------------------------------------------
__global__ void __launch_bounds__(256)
hist4_kernel(const int* __restrict__ r1, const int* __restrict__ r2,
             int E1, int E2)
{
    const int V1 = (E1 + 3) >> 2;
    const int V2 = (E2 + 3) >> 2;
    int v = blockIdx.x * blockDim.x + threadIdx.x;
    const int* rows; int E, rowbase;
    if (v < V1)            { rows = r1; E = E1; rowbase = 0; }
    else if (v < V1 + V2)  { rows = r2; E = E2; rowbase = N_NODES; v -= V1; }
    else return;

    const int i = v * 4;
    if (i + 3 < E) {
        const int4 r = __ldg(reinterpret_cast<const int4*>(rows) + v);
        atomicAdd(&g_cnt[rowbase + r.x], 1);
        atomicAdd(&g_cnt[rowbase + r.y], 1);
        atomicAdd(&g_cnt[rowbase + r.z], 1);
        atomicAdd(&g_cnt[rowbase + r.w], 1);
    } else {
        for (int k = i; k < E; ++k)
            atomicAdd(&g_cnt[rowbase + __ldg(rows + k)], 1);
    }
}

// ---------------------------------------------------------------------------
// Scan stage A: coalesced block-local exclusive scan of g_cnt -> g_off,
// block totals -> g_bsum. (Proven: ~5 us.)
// ---------------------------------------------------------------------------
__global__ void __launch_bounds__(SCAN_B)
scanA_kernel()
{
    __shared__ int sh[SCAN_B];
    const int t = threadIdx.x;
    const int i = blockIdx.x * SCAN_B + t;
    const int v = (i < NROWS2) ? g_cnt[i] : 0;
    sh[t] = v;
    __syncthreads();
    #pragma unroll
    for (int d = 1; d < SCAN_B; d <<= 1) {
        int u = (t >= d) ? sh[t - d] : 0;
        __syncthreads();
        sh[t] += u;
        __syncthreads();
    }
    if (i < NROWS2) g_off[i] = sh[t] - v;           // block-local exclusive
    if (t == SCAN_B - 1) g_bsum[blockIdx.x] = sh[t];
}

// ---------------------------------------------------------------------------
// Scan stage BC (merged): each block INDEPENDENTLY reduces bsum[j < bid]
// (391 ints: <=2 loads/thread + shared tree) and applies the base. No
// inter-block ordering, no serial single-block kernel, no spin-waiting.
// ---------------------------------------------------------------------------
__global__ void __launch_bounds__(SCAN_B)
scanBC_kernel()
{
    __shared__ int sh[SCAN_B];
    const int t   = threadIdx.x;
    const int bid = blockIdx.x;

    // Sum of predecessor block totals (j < bid); NBLK=391 <= 2*SCAN_B.
    int s = 0;
    if (t         < bid && t         < NBLK) s += g_bsum[t];
    if (t + SCAN_B < bid && t + SCAN_B < NBLK) s += g_bsum[t + SCAN_B];
    sh[t] = s;
    __syncthreads();
    #pragma unroll
    for (int d = SCAN_B / 2; d > 0; d >>= 1) {
        if (t < d) sh[t] += sh[t + d];
        __syncthreads();
    }
    const int base = sh[0];

    const int i = bid * SCAN_B + t;
    if (i < NROWS2) {
        const int o = g_off[i] + base;
        g_off[i] = o;
        g_pos[i] = o;
    }
    if (bid == NBLK - 1 && t == 0)
        g_off[NROWS2] = base + g_bsum[NBLK - 1];       // grand total sentinel
}

// ---------------------------------------------------------------------------
// Scatter over BOTH relations (standalone: lean regs, high occupancy).
// ---------------------------------------------------------------------------
__global__ void __launch_bounds__(256)
scatter4_kernel(const int* __restrict__ r1, const int* __restrict__ c1,
                const float* __restrict__ v1,
                const int* __restrict__ r2, const int* __restrict__ c2,
                const float* __restrict__ v2,
                int E1, int E2)
{
    const int V1 = (E1 + 3) >> 2;
    const int V2 = (E2 + 3) >> 2;
    int v = blockIdx.x * blockDim.x + threadIdx.x;
    const int* rows; const int* cols; const float* vals; int E, rowbase;
    if (v < V1)           { rows = r1; cols = c1; vals = v1; E = E1; rowbase = 0; }
    else if (v < V1 + V2) { rows = r2; cols = c2; vals = v2; E = E2; rowbase = N_NODES; v -= V1; }
    else return;

    const int i = v * 4;
    if (i + 3 < E) {
        const int4   r = __ldg(reinterpret_cast<const int4*>(rows) + v);
        const int4   c = __ldg(reinterpret_cast<const int4*>(cols) + v);
        const float4 w = __ldg(reinterpret_cast<const float4*>(vals) + v);
        const int p0 = atomicAdd(&g_pos[rowbase + r.x], 1);
        const int p1 = atomicAdd(&g_pos[rowbase + r.y], 1);
        const int p2 = atomicAdd(&g_pos[rowbase + r.z], 1);
        const int p3 = atomicAdd(&g_pos[rowbase + r.w], 1);
        g_edge[p0] = make_int2(c.x, __float_as_int(w.x));
        g_edge[p1] = make_int2(c.y, __float_as_int(w.y));
        g_edge[p2] = make_int2(c.z, __float_as_int(w.z));
        g_edge[p3] = make_int2(c.w, __float_as_int(w.w));
    } else {
        for (int k = i; k < E; ++k) {
            const int p = atomicAdd(&g_pos[rowbase + __ldg(rows + k)], 1);
            g_edge[p] = make_int2(__ldg(cols + k), __float_as_int(__ldg(vals + k)));
        }
    }
}

// ---------------------------------------------------------------------------
// Dense projection on tensor cores (EXACT R9 form — measured 41.6 us; the
// paired-LDS.64 variant regressed to 57 via bank conflicts, reverted).
// ---------------------------------------------------------------------------
__global__ void __launch_bounds__(256)
gemm_tf32_kernel(const float* __restrict__ in,
                 const float* __restrict__ W1,
                 const float* __restrict__ W2)
{
    __shared__ uint32_t shA[64 * A_PAD];

    const int tid  = threadIdx.x;
    const int warp = tid >> 5;
    const int lane = tid & 31;
    const float* __restrict__ W    = blockIdx.y ? W2   : W1;
    float*       __restrict__ xout = blockIdx.y ? g_x2 : g_x1;

    const int col0 = warp * 16;
    uint32_t Bf[2][16][2];
    #pragma unroll
    for (int nt = 0; nt < 2; ++nt) {
        const int n = col0 + nt * 8 + (lane >> 2);
        #pragma unroll
        for (int kk = 0; kk < 16; ++kk) {
            const int k = kk * 8 + (lane & 3);
            Bf[nt][kk][0] = f2tf32(__ldg(W + k * DIM + n));
            Bf[nt][kk][1] = f2tf32(__ldg(W + (k + 4) * DIM + n));
        }
    }

    #pragma unroll
    for (int t = 0; t < 2; ++t) {
        const int row0 = blockIdx.x * 128 + t * 64;

        #pragma unroll
        for (int i = 0; i < 8; ++i) {
            int idx = tid + i * 256;
            int r   = idx >> 5;
            int c4  = idx & 31;
            float4 v = make_float4(0.f, 0.f, 0.f, 0.f);
            if (row0 + r < N_NODES)
                v = __ldg(reinterpret_cast<const float4*>(in + (size_t)(row0 + r) * DIM) + c4);
            uint32_t* s = shA + r * A_PAD + c4 * 4;
            s[0] = f2tf32(v.x); s[1] = f2tf32(v.y);
            s[2] = f2tf32(v.z); s[3] = f2tf32(v.w);
        }
        __syncthreads();

        #pragma unroll
        for (int rt = 0; rt < 4; ++rt) {
            float acc[2][4] = {};
            const uint32_t* sA = shA + (rt * 16) * A_PAD;
            #pragma unroll
            for (int kk = 0; kk < 16; ++kk) {
                const int r = lane >> 2, c = kk * 8 + (lane & 3);
                uint32_t a0 = sA[r * A_PAD + c];
                uint32_t a1 = sA[(r + 8) * A_PAD + c];
                uint32_t a2 = sA[r * A_PAD + c + 4];
                uint32_t a3 = sA[(r + 8) * A_PAD + c + 4];
                #pragma unroll
                for (int nt = 0; nt < 2; ++nt) {
                    asm volatile(
                        "mma.sync.aligned.m16n8k8.row.col.f32.tf32.tf32.f32 "
                        "{%0,%1,%2,%3}, {%4,%5,%6,%7}, {%8,%9}, {%0,%1,%2,%3};"
                        : "+f"(acc[nt][0]), "+f"(acc[nt][1]),
                          "+f"(acc[nt][2]), "+f"(acc[nt][3])
                        : "r"(a0), "r"(a1), "r"(a2), "r"(a3),
                          "r"(Bf[nt][kk][0]), "r"(Bf[nt][kk][1]));
                }
            }
            const int rowa = row0 + rt * 16 + (lane >> 2);
            const int rowb = rowa + 8;
            #pragma unroll
            for (int nt = 0; nt < 2; ++nt) {
                const int c = col0 + nt * 8 + 2 * (lane & 3);
                if (rowa < N_NODES)
                    *reinterpret_cast<float2*>(xout + (size_t)rowa * DIM + c) =
                        make_float2(acc[nt][0], acc[nt][1]);
                if (rowb < N_NODES)
                    *reinterpret_cast<float2*>(xout + (size_t)rowb * DIM + c) =
                        make_float2(acc[nt][2], acc[nt][3]);
            }
        }
        __syncthreads();   // shA reused by next tile
    }
}

// ---------------------------------------------------------------------------
// Segmented SpMM, warp-cooperative (unchanged: 62 us, at LTS gather floor).
// Also restores the g_cnt == 0 invariant.
// ---------------------------------------------------------------------------
__device__ __forceinline__ void row_accum(const float* __restrict__ x,
                                          int s, int e, int lane,
                                          int* __restrict__ shc,
                                          int* __restrict__ shv,
                                          float4& acc)
{
    for (int i = s; i < e; i += 32) {
        const int idx = i + lane;
        if (idx < e) {
            const int2 t = __ldg(&g_edge[idx]);
            shc[lane] = t.x;
            shv[lane] = t.y;
        }
        __syncwarp();
        const int m = min(e - i, 32);
        int j = 0;
        for (; j + 4 <= m; j += 4) {
            const int c0 = shc[j],     c1 = shc[j + 1];
            const int c2 = shc[j + 2], c3 = shc[j + 3];
            const float4 x0 = __ldg(reinterpret_cast<const float4*>(x + (size_t)c0 * DIM) + lane);
            const float4 x1 = __ldg(reinterpret_cast<const float4*>(x + (size_t)c1 * DIM) + lane);
            const float4 x2 = __ldg(reinterpret_cast<const float4*>(x + (size_t)c2 * DIM) + lane);
            const float4 x3 = __ldg(reinterpret_cast<const float4*>(x + (size_t)c3 * DIM) + lane);
            const float v0 = __int_as_float(shv[j]);
            const float v1 = __int_as_float(shv[j + 1]);
            const float v2 = __int_as_float(shv[j + 2]);
            const float v3 = __int_as_float(shv[j + 3]);
            acc.x = fmaf(v0, x0.x, acc.x); acc.y = fmaf(v0, x0.y, acc.y);
            acc.z = fmaf(v0, x0.z, acc.z); acc.w = fmaf(v0, x0.w, acc.w);
            acc.x = fmaf(v1, x1.x, acc.x); acc.y = fmaf(v1, x1.y, acc.y);
            acc.z = fmaf(v1, x1.z, acc.z); acc.w = fmaf(v1, x1.w, acc.w);
            acc.x = fmaf(v2, x2.x, acc.x); acc.y = fmaf(v2, x2.y, acc.y);
            acc.z = fmaf(v2, x2.z, acc.z); acc.w = fmaf(v2, x2.w, acc.w);
            acc.x = fmaf(v3, x3.x, acc.x); acc.y = fmaf(v3, x3.y, acc.y);
            acc.z = fmaf(v3, x3.z, acc.z); acc.w = fmaf(v3, x3.w, acc.w);
        }
        for (; j < m; ++j) {
            const int   c  = shc[j];
            const float v  = __int_as_float(shv[j]);
            const float4 xv = __ldg(reinterpret_cast<const float4*>(x + (size_t)c * DIM) + lane);
            acc.x = fmaf(v, xv.x, acc.x); acc.y = fmaf(v, xv.y, acc.y);
            acc.z = fmaf(v, xv.z, acc.z); acc.w = fmaf(v, xv.w, acc.w);
        }
        __syncwarp();
    }
}

__global__ void __launch_bounds__(256)
spmm_csr_kernel(float* __restrict__ out)
{
    __shared__ int shc[8][32];
    __shared__ int shv[8][32];

    const int warp = threadIdx.x >> 5;
    const int lane = threadIdx.x & 31;
    const int row  = blockIdx.x * 8 + warp;

    // Restore g_cnt == 0 invariant for the next call (not read here).
    // 6250 blocks x 16 lanes = 100000 = NROWS2 exactly.
    if (warp == 0 && lane < 16) {
        const int z = blockIdx.x * 16 + lane;
        if (z < NROWS2) g_cnt[z] = 0;
    }

    if (row >= N_NODES) return;

    float4 acc = make_float4(0.f, 0.f, 0.f, 0.f);

    row_accum(g_x1, g_off[row],           g_off[row + 1],
              lane, shc[warp], shv[warp], acc);
    row_accum(g_x2, g_off[N_NODES + row], g_off[N_NODES + row + 1],
              lane, shc[warp], shv[warp], acc);

    acc.x = fmaxf(acc.x, 0.f); acc.y = fmaxf(acc.y, 0.f);
    acc.z = fmaxf(acc.z, 0.f); acc.w = fmaxf(acc.w, 0.f);
    reinterpret_cast<float4*>(out + (size_t)row * DIM)[lane] = acc;
}

// ---------------------------------------------------------------------------
// Entry point. Inputs (metadata order):
//   0 inputs[N,128] f32 | 1 adj1_rows i32 | 2 adj1_cols i32 | 3 adj1_vals f32
//   4 adj2_rows i32 | 5 adj2_cols i32 | 6 adj2_vals f32
//   7 weights_1[128,128] f32 | 8 weights_2[128,128] f32
// Output: [N,128] f32.  6 launches total.
// ---------------------------------------------------------------------------
extern "C" void kernel_launch(void* const* d_in, const int* in_sizes, int n_in,
                              void* d_out, int out_size)
{
    const float* in  = (const float*)d_in[0];
    const int*   a1r = (const int*)  d_in[1];
    const int*   a1c = (const int*)  d_in[2];
    const float* a1v = (const float*)d_in[3];
    const int*   a2r = (const int*)  d_in[4];
    const int*   a2c = (const int*)  d_in[5];
    const float* a2v = (const float*)d_in[6];
    const float* W1  = (const float*)d_in[7];
    const float* W2  = (const float*)d_in[8];
    float*       out = (float*)d_out;

    const int E1 = in_sizes[1];
    const int E2 = in_sizes[4];

    const int Vtot = (E1 + 3) / 4 + (E2 + 3) / 4;
    const int eblk = (Vtot + 255) / 256;

    // 1. Histogram (g_cnt zero by invariant).
    hist4_kernel<<<eblk, 256>>>(a1r, a2r, E1, E2);

    // 2-3. Two-stage scan: block-local scan, then independent per-block
    //      base reduction (no serial single-block kernel, no spinning).
    scanA_kernel<<<NBLK, SCAN_B>>>();
    scanBC_kernel<<<NBLK, SCAN_B>>>();

    // 4. Edge scatter into CSR order.
    scatter4_kernel<<<eblk, 256>>>(a1r, a1c, a1v, a2r, a2c, a2v, E1, E2);

    // 5. Tensor-core projections (proven 41.6 us form).
    dim3 ggrid((N_NODES + 127) / 128, 2);
    gemm_tf32_kernel<<<ggrid, 256>>>(in, W1, W2);

    // 6. Segmented SpMM + fused ReLU + invariant restore.
    spmm_csr_kernel<<<(N_NODES + 7) / 8, 256>>>(out);
}

// round 13
// speedup vs baseline: 1.1901x; 1.0278x over previous
#include <cuda_runtime.h>
#include <stdint.h>

#define N_NODES 50000
#define DIM     128        // D == O == 128
#define E_MAX   800016     // per-relation edge capacity (problem fixes E=800000)
#define A_PAD   132        // shared A row stride (bank-conflict-free scalar frags)

#define NROWS2  (2 * N_NODES)                      // flattened rows (2 relations)
#define SCAN_B  256
#define NBLK    ((NROWS2 + SCAN_B - 1) / SCAN_B)   // 391

// ---------------------------------------------------------------------------
// Static scratch (no cudaMalloc allowed). g_cnt is ZERO at entry to every
// kernel_launch call: zero-initialized static on the first call, and
// spmm_csr_kernel (which does not read it) re-zeros it on every call.
// ---------------------------------------------------------------------------
__device__ float g_x1[N_NODES * DIM];        // in @ W1   (25.6 MB)
__device__ float g_x2[N_NODES * DIM];        // in @ W2   (25.6 MB)

__device__ int  g_cnt[NROWS2];               // per-row edge counts
__device__ int  g_off[NROWS2 + 1];           // CSR row pointers
__device__ int  g_pos[NROWS2];               // scatter cursors
__device__ int  g_bsum[NBLK];                // scanA block sums
__device__ int2 g_edge[2 * E_MAX];           // packed (col, val-bits)

__device__ __forceinline__ uint32_t f2tf32(float f) {
    uint32_t r;
    asm("cvt.rna.tf32.f32 %0, %1;" : "=r"(r) : "f"(f));
    return r;
}

// ---------------------------------------------------------------------------
// Histogram over BOTH relations: thread owns one 4-edge vector group.
// Requires g_cnt == 0 (invariant).
// ---------------------------------------------------------------------------
__global__ void __launch_bounds__(256)
hist4_kernel(const int* __restrict__ r1, const int* __restrict__ r2,
             int E1, int E2)
{
    const int V1 = (E1 + 3) >> 2;
    const int V2 = (E2 + 3) >> 2;
    int v = blockIdx.x * blockDim.x + threadIdx.x;
    const int* rows; int E, rowbase;
    if (v < V1)            { rows = r1; E = E1; rowbase = 0; }
    else if (v < V1 + V2)  { rows = r2; E = E2; rowbase = N_NODES; v -= V1; }
    else return;

    const int i = v * 4;
    if (i + 3 < E) {
        const int4 r = __ldg(reinterpret_cast<const int4*>(rows) + v);
        atomicAdd(&g_cnt[rowbase + r.x], 1);
        atomicAdd(&g_cnt[rowbase + r.y], 1);
        atomicAdd(&g_cnt[rowbase + r.z], 1);
        atomicAdd(&g_cnt[rowbase + r.w], 1);
    } else {
        for (int k = i; k < E; ++k)
            atomicAdd(&g_cnt[rowbase + __ldg(rows + k)], 1);
    }
}

// ---------------------------------------------------------------------------
// Scan stage A: coalesced block-local exclusive scan of g_cnt -> g_off,
// block totals -> g_bsum.
// ---------------------------------------------------------------------------
__global__ void __launch_bounds__(SCAN_B)
scanA_kernel()
{
    __shared__ int sh[SCAN_B];
    const int t = threadIdx.x;
    const int i = blockIdx.x * SCAN_B + t;
    const int v = (i < NROWS2) ? g_cnt[i] : 0;
    sh[t] = v;
    __syncthreads();
    #pragma unroll
    for (int d = 1; d < SCAN_B; d <<= 1) {
        int u = (t >= d) ? sh[t - d] : 0;
        __syncthreads();
        sh[t] += u;
        __syncthreads();
    }
    if (i < NROWS2) g_off[i] = sh[t] - v;           // block-local exclusive
    if (t == SCAN_B - 1) g_bsum[blockIdx.x] = sh[t];
}

// ---------------------------------------------------------------------------
// Scan stage BC (merged): each block INDEPENDENTLY reduces bsum[j < bid]
// and applies the base. No inter-block ordering, no spinning.
// ---------------------------------------------------------------------------
__global__ void __launch_bounds__(SCAN_B)
scanBC_kernel()
{
    __shared__ int sh[SCAN_B];
    const int t   = threadIdx.x;
    const int bid = blockIdx.x;

    int s = 0;
    if (t         < bid && t         < NBLK) s += g_bsum[t];
    if (t + SCAN_B < bid && t + SCAN_B < NBLK) s += g_bsum[t + SCAN_B];
    sh[t] = s;
    __syncthreads();
    #pragma unroll
    for (int d = SCAN_B / 2; d > 0; d >>= 1) {
        if (t < d) sh[t] += sh[t + d];
        __syncthreads();
    }
    const int base = sh[0];

    const int i = bid * SCAN_B + t;
    if (i < NROWS2) {
        const int o = g_off[i] + base;
        g_off[i] = o;
        g_pos[i] = o;
    }
    if (bid == NBLK - 1 && t == 0)
        g_off[NROWS2] = base + g_bsum[NBLK - 1];       // grand total sentinel
}

// ---------------------------------------------------------------------------
// Scatter over BOTH relations (standalone: lean regs, high occupancy).
// ---------------------------------------------------------------------------
__global__ void __launch_bounds__(256)
scatter4_kernel(const int* __restrict__ r1, const int* __restrict__ c1,
                const float* __restrict__ v1,
                const int* __restrict__ r2, const int* __restrict__ c2,
                const float* __restrict__ v2,
                int E1, int E2)
{
    const int V1 = (E1 + 3) >> 2;
    const int V2 = (E2 + 3) >> 2;
    int v = blockIdx.x * blockDim.x + threadIdx.x;
    const int* rows; const int* cols; const float* vals; int E, rowbase;
    if (v < V1)           { rows = r1; cols = c1; vals = v1; E = E1; rowbase = 0; }
    else if (v < V1 + V2) { rows = r2; cols = c2; vals = v2; E = E2; rowbase = N_NODES; v -= V1; }
    else return;

    const int i = v * 4;
    if (i + 3 < E) {
        const int4   r = __ldg(reinterpret_cast<const int4*>(rows) + v);
        const int4   c = __ldg(reinterpret_cast<const int4*>(cols) + v);
        const float4 w = __ldg(reinterpret_cast<const float4*>(vals) + v);
        const int p0 = atomicAdd(&g_pos[rowbase + r.x], 1);
        const int p1 = atomicAdd(&g_pos[rowbase + r.y], 1);
        const int p2 = atomicAdd(&g_pos[rowbase + r.z], 1);
        const int p3 = atomicAdd(&g_pos[rowbase + r.w], 1);
        g_edge[p0] = make_int2(c.x, __float_as_int(w.x));
        g_edge[p1] = make_int2(c.y, __float_as_int(w.y));
        g_edge[p2] = make_int2(c.z, __float_as_int(w.z));
        g_edge[p3] = make_int2(c.w, __float_as_int(w.w));
    } else {
        for (int k = i; k < E; ++k) {
            const int p = atomicAdd(&g_pos[rowbase + __ldg(rows + k)], 1);
            g_edge[p] = make_int2(__ldg(cols + k), __float_as_int(__ldg(vals + k)));
        }
    }
}

// ---------------------------------------------------------------------------
// Dense projection on tensor cores (proven 41.6 us form, unchanged).
// ---------------------------------------------------------------------------
__global__ void __launch_bounds__(256)
gemm_tf32_kernel(const float* __restrict__ in,
                 const float* __restrict__ W1,
                 const float* __restrict__ W2)
{
    __shared__ uint32_t shA[64 * A_PAD];

    const int tid  = threadIdx.x;
    const int warp = tid >> 5;
    const int lane = tid & 31;
    const float* __restrict__ W    = blockIdx.y ? W2   : W1;
    float*       __restrict__ xout = blockIdx.y ? g_x2 : g_x1;

    const int col0 = warp * 16;
    uint32_t Bf[2][16][2];
    #pragma unroll
    for (int nt = 0; nt < 2; ++nt) {
        const int n = col0 + nt * 8 + (lane >> 2);
        #pragma unroll
        for (int kk = 0; kk < 16; ++kk) {
            const int k = kk * 8 + (lane & 3);
            Bf[nt][kk][0] = f2tf32(__ldg(W + k * DIM + n));
            Bf[nt][kk][1] = f2tf32(__ldg(W + (k + 4) * DIM + n));
        }
    }

    #pragma unroll
    for (int t = 0; t < 2; ++t) {
        const int row0 = blockIdx.x * 128 + t * 64;

        #pragma unroll
        for (int i = 0; i < 8; ++i) {
            int idx = tid + i * 256;
            int r   = idx >> 5;
            int c4  = idx & 31;
            float4 v = make_float4(0.f, 0.f, 0.f, 0.f);
            if (row0 + r < N_NODES)
                v = __ldg(reinterpret_cast<const float4*>(in + (size_t)(row0 + r) * DIM) + c4);
            uint32_t* s = shA + r * A_PAD + c4 * 4;
            s[0] = f2tf32(v.x); s[1] = f2tf32(v.y);
            s[2] = f2tf32(v.z); s[3] = f2tf32(v.w);
        }
        __syncthreads();

        #pragma unroll
        for (int rt = 0; rt < 4; ++rt) {
            float acc[2][4] = {};
            const uint32_t* sA = shA + (rt * 16) * A_PAD;
            #pragma unroll
            for (int kk = 0; kk < 16; ++kk) {
                const int r = lane >> 2, c = kk * 8 + (lane & 3);
                uint32_t a0 = sA[r * A_PAD + c];
                uint32_t a1 = sA[(r + 8) * A_PAD + c];
                uint32_t a2 = sA[r * A_PAD + c + 4];
                uint32_t a3 = sA[(r + 8) * A_PAD + c + 4];
                #pragma unroll
                for (int nt = 0; nt < 2; ++nt) {
                    asm volatile(
                        "mma.sync.aligned.m16n8k8.row.col.f32.tf32.tf32.f32 "
                        "{%0,%1,%2,%3}, {%4,%5,%6,%7}, {%8,%9}, {%0,%1,%2,%3};"
                        : "+f"(acc[nt][0]), "+f"(acc[nt][1]),
                          "+f"(acc[nt][2]), "+f"(acc[nt][3])
                        : "r"(a0), "r"(a1), "r"(a2), "r"(a3),
                          "r"(Bf[nt][kk][0]), "r"(Bf[nt][kk][1]));
                }
            }
            const int rowa = row0 + rt * 16 + (lane >> 2);
            const int rowb = rowa + 8;
            #pragma unroll
            for (int nt = 0; nt < 2; ++nt) {
                const int c = col0 + nt * 8 + 2 * (lane & 3);
                if (rowa < N_NODES)
                    *reinterpret_cast<float2*>(xout + (size_t)rowa * DIM + c) =
                        make_float2(acc[nt][0], acc[nt][1]);
                if (rowb < N_NODES)
                    *reinterpret_cast<float2*>(xout + (size_t)rowb * DIM + c) =
                        make_float2(acc[nt][2], acc[nt][3]);
            }
        }
        __syncthreads();   // shA reused by next tile
    }
}

// ---------------------------------------------------------------------------
// Segmented SpMM, warp-cooperative (unchanged: 62 us, at LTS gather floor).
// Also restores the g_cnt == 0 invariant.
// ---------------------------------------------------------------------------
__device__ __forceinline__ void row_accum(const float* __restrict__ x,
                                          int s, int e, int lane,
                                          int* __restrict__ shc,
                                          int* __restrict__ shv,
                                          float4& acc)
{
    for (int i = s; i < e; i += 32) {
        const int idx = i + lane;
        if (idx < e) {
            const int2 t = __ldg(&g_edge[idx]);
            shc[lane] = t.x;
            shv[lane] = t.y;
        }
        __syncwarp();
        const int m = min(e - i, 32);
        int j = 0;
        for (; j + 4 <= m; j += 4) {
            const int c0 = shc[j],     c1 = shc[j + 1];
            const int c2 = shc[j + 2], c3 = shc[j + 3];
            const float4 x0 = __ldg(reinterpret_cast<const float4*>(x + (size_t)c0 * DIM) + lane);
            const float4 x1 = __ldg(reinterpret_cast<const float4*>(x + (size_t)c1 * DIM) + lane);
            const float4 x2 = __ldg(reinterpret_cast<const float4*>(x + (size_t)c2 * DIM) + lane);
            const float4 x3 = __ldg(reinterpret_cast<const float4*>(x + (size_t)c3 * DIM) + lane);
            const float v0 = __int_as_float(shv[j]);
            const float v1 = __int_as_float(shv[j + 1]);
            const float v2 = __int_as_float(shv[j + 2]);
            const float v3 = __int_as_float(shv[j + 3]);
            acc.x = fmaf(v0, x0.x, acc.x); acc.y = fmaf(v0, x0.y, acc.y);
            acc.z = fmaf(v0, x0.z, acc.z); acc.w = fmaf(v0, x0.w, acc.w);
            acc.x = fmaf(v1, x1.x, acc.x); acc.y = fmaf(v1, x1.y, acc.y);
            acc.z = fmaf(v1, x1.z, acc.z); acc.w = fmaf(v1, x1.w, acc.w);
            acc.x = fmaf(v2, x2.x, acc.x); acc.y = fmaf(v2, x2.y, acc.y);
            acc.z = fmaf(v2, x2.z, acc.z); acc.w = fmaf(v2, x2.w, acc.w);
            acc.x = fmaf(v3, x3.x, acc.x); acc.y = fmaf(v3, x3.y, acc.y);
            acc.z = fmaf(v3, x3.z, acc.z); acc.w = fmaf(v3, x3.w, acc.w);
        }
        for (; j < m; ++j) {
            const int   c  = shc[j];
            const float v  = __int_as_float(shv[j]);
            const float4 xv = __ldg(reinterpret_cast<const float4*>(x + (size_t)c * DIM) + lane);
            acc.x = fmaf(v, xv.x, acc.x); acc.y = fmaf(v, xv.y, acc.y);
            acc.z = fmaf(v, xv.z, acc.z); acc.w = fmaf(v, xv.w, acc.w);
        }
        __syncwarp();
    }
}

__global__ void __launch_bounds__(256)
spmm_csr_kernel(float* __restrict__ out)
{
    __shared__ int shc[8][32];
    __shared__ int shv[8][32];

    const int warp = threadIdx.x >> 5;
    const int lane = threadIdx.x & 31;
    const int row  = blockIdx.x * 8 + warp;

    // Restore g_cnt == 0 invariant for the next call (not read here).
    if (warp == 0 && lane < 16) {
        const int z = blockIdx.x * 16 + lane;
        if (z < NROWS2) g_cnt[z] = 0;
    }

    if (row >= N_NODES) return;

    float4 acc = make_float4(0.f, 0.f, 0.f, 0.f);

    row_accum(g_x1, g_off[row],           g_off[row + 1],
              lane, shc[warp], shv[warp], acc);
    row_accum(g_x2, g_off[N_NODES + row], g_off[N_NODES + row + 1],
              lane, shc[warp], shv[warp], acc);

    acc.x = fmaxf(acc.x, 0.f); acc.y = fmaxf(acc.y, 0.f);
    acc.z = fmaxf(acc.z, 0.f); acc.w = fmaxf(acc.w, 0.f);
    reinterpret_cast<float4*>(out + (size_t)row * DIM)[lane] = acc;
}

// ---------------------------------------------------------------------------
// Entry point. Fork-join stream capture: the GEMM (independent of the CSR
// build chain) runs on a side stream in parallel with hist/scan/scatter;
// the SpMM joins both branches. Stream/events are created once (host-side
// resources, idempotent, no device memory). Every call records the exact
// same graph topology -> deterministic.
//
// Inputs (metadata order):
//   0 inputs[N,128] f32 | 1 adj1_rows i32 | 2 adj1_cols i32 | 3 adj1_vals f32
//   4 adj2_rows i32 | 5 adj2_cols i32 | 6 adj2_vals f32
//   7 weights_1[128,128] f32 | 8 weights_2[128,128] f32
// Output: [N,128] f32.
// ---------------------------------------------------------------------------
static cudaStream_t s_side   = nullptr;
static cudaEvent_t  s_evFork = nullptr;
static cudaEvent_t  s_evJoin = nullptr;

extern "C" void kernel_launch(void* const* d_in, const int* in_sizes, int n_in,
                              void* d_out, int out_size)
{
    if (s_side == nullptr) {                   // one-time host resource init
        cudaStreamCreateWithFlags(&s_side, cudaStreamNonBlocking);
        cudaEventCreateWithFlags(&s_evFork, cudaEventDisableTiming);
        cudaEventCreateWithFlags(&s_evJoin, cudaEventDisableTiming);
    }

    const float* in  = (const float*)d_in[0];
    const int*   a1r = (const int*)  d_in[1];
    const int*   a1c = (const int*)  d_in[2];
    const float* a1v = (const float*)d_in[3];
    const int*   a2r = (const int*)  d_in[4];
    const int*   a2c = (const int*)  d_in[5];
    const float* a2v = (const float*)d_in[6];
    const float* W1  = (const float*)d_in[7];
    const float* W2  = (const float*)d_in[8];
    float*       out = (float*)d_out;

    const int E1 = in_sizes[1];
    const int E2 = in_sizes[4];

    const int Vtot = (E1 + 3) / 4 + (E2 + 3) / 4;
    const int eblk = (Vtot + 255) / 256;

    // ---- fork: GEMM branch on side stream ---------------------------------
    cudaEventRecord(s_evFork, 0);              // origin = capture (legacy) stream
    cudaStreamWaitEvent(s_side, s_evFork, 0);

    dim3 ggrid((N_NODES + 127) / 128, 2);
    gemm_tf32_kernel<<<ggrid, 256, 0, s_side>>>(in, W1, W2);
    cudaEventRecord(s_evJoin, s_side);

    // ---- main branch: CSR build chain (independent of GEMM) ----------------
    hist4_kernel<<<eblk, 256>>>(a1r, a2r, E1, E2);
    scanA_kernel<<<NBLK, SCAN_B>>>();
    scanBC_kernel<<<NBLK, SCAN_B>>>();
    scatter4_kernel<<<eblk, 256>>>(a1r, a1c, a1v, a2r, a2c, a2v, E1, E2);

    // ---- join: SpMM needs both g_edge (build) and g_x1/g_x2 (GEMM) --------
    cudaStreamWaitEvent(0, s_evJoin, 0);
    spmm_csr_kernel<<<(N_NODES + 7) / 8, 256>>>(out);
}

// round 14
// speedup vs baseline: 1.2210x; 1.0259x over previous
#include <cuda_runtime.h>
#include <stdint.h>

#define N_NODES 50000
#define DIM     128        // D == O == 128
#define E_MAX   800016     // per-relation edge capacity (problem fixes E=800000)
#define A_PAD   132        // shared A row stride (bank-conflict-free scalar frags)

#define NROWS2  (2 * N_NODES)                      // flattened rows (2 relations)
#define SCAN_B  256
#define NBLK    ((NROWS2 + SCAN_B - 1) / SCAN_B)   // 391

// ---------------------------------------------------------------------------
// Static scratch (no cudaMalloc allowed). g_cnt is ZERO at entry to every
// kernel_launch call: zero-initialized static on the first call, and
// spmm_csr_kernel (which does not read it) re-zeros it on every call.
// ---------------------------------------------------------------------------
__device__ float g_x1[N_NODES * DIM];        // in @ W1   (25.6 MB)
__device__ float g_x2[N_NODES * DIM];        // in @ W2   (25.6 MB)

__device__ int  g_cnt[NROWS2];               // per-row edge counts
__device__ int  g_off[NROWS2 + 1];           // CSR row pointers
__device__ int  g_bsum[NBLK];                // scanA block sums
__device__ int  g_rank1[E_MAX];              // per-edge rank within row (rel 1)
__device__ int  g_rank2[E_MAX];              // per-edge rank within row (rel 2)
__device__ int2 g_edge[2 * E_MAX];           // packed (col, val-bits)

__device__ __forceinline__ uint32_t f2tf32(float f) {
    uint32_t r;
    asm("cvt.rna.tf32.f32 %0, %1;" : "=r"(r) : "f"(f));
    return r;
}

// ---------------------------------------------------------------------------
// Histogram over BOTH relations. The atomicAdd return value IS each edge's
// rank within its row -- store it (coalesced int4) so the scatter pass needs
// NO atomics. Requires g_cnt == 0 (invariant).
// ---------------------------------------------------------------------------
__global__ void __launch_bounds__(256)
hist4_kernel(const int* __restrict__ r1, const int* __restrict__ r2,
             int E1, int E2)
{
    const int V1 = (E1 + 3) >> 2;
    const int V2 = (E2 + 3) >> 2;
    int v = blockIdx.x * blockDim.x + threadIdx.x;
    const int* rows; int* rank; int E, rowbase;
    if (v < V1)            { rows = r1; rank = g_rank1; E = E1; rowbase = 0; }
    else if (v < V1 + V2)  { rows = r2; rank = g_rank2; E = E2; rowbase = N_NODES; v -= V1; }
    else return;

    const int i = v * 4;
    if (i + 3 < E) {
        const int4 r = __ldg(reinterpret_cast<const int4*>(rows) + v);
        int4 k;
        k.x = atomicAdd(&g_cnt[rowbase + r.x], 1);
        k.y = atomicAdd(&g_cnt[rowbase + r.y], 1);
        k.z = atomicAdd(&g_cnt[rowbase + r.z], 1);
        k.w = atomicAdd(&g_cnt[rowbase + r.w], 1);
        reinterpret_cast<int4*>(rank)[v] = k;
    } else {
        for (int e = i; e < E; ++e)
            rank[e] = atomicAdd(&g_cnt[rowbase + __ldg(rows + e)], 1);
    }
}

// ---------------------------------------------------------------------------
// Scan stage A: coalesced block-local exclusive scan of g_cnt -> g_off,
// block totals -> g_bsum.
// ---------------------------------------------------------------------------
__global__ void __launch_bounds__(SCAN_B)
scanA_kernel()
{
    __shared__ int sh[SCAN_B];
    const int t = threadIdx.x;
    const int i = blockIdx.x * SCAN_B + t;
    const int v = (i < NROWS2) ? g_cnt[i] : 0;
    sh[t] = v;
    __syncthreads();
    #pragma unroll
    for (int d = 1; d < SCAN_B; d <<= 1) {
        int u = (t >= d) ? sh[t - d] : 0;
        __syncthreads();
        sh[t] += u;
        __syncthreads();
    }
    if (i < NROWS2) g_off[i] = sh[t] - v;           // block-local exclusive
    if (t == SCAN_B - 1) g_bsum[blockIdx.x] = sh[t];
}

// ---------------------------------------------------------------------------
// Scan stage BC (merged): each block INDEPENDENTLY reduces bsum[j < bid]
// and applies the base. No inter-block ordering, no spinning.
// ---------------------------------------------------------------------------
__global__ void __launch_bounds__(SCAN_B)
scanBC_kernel()
{
    __shared__ int sh[SCAN_B];
    const int t   = threadIdx.x;
    const int bid = blockIdx.x;

    int s = 0;
    if (t         < bid && t         < NBLK) s += g_bsum[t];
    if (t + SCAN_B < bid && t + SCAN_B < NBLK) s += g_bsum[t + SCAN_B];
    sh[t] = s;
    __syncthreads();
    #pragma unroll
    for (int d = SCAN_B / 2; d > 0; d >>= 1) {
        if (t < d) sh[t] += sh[t + d];
        __syncthreads();
    }
    const int base = sh[0];

    const int i = bid * SCAN_B + t;
    if (i < NROWS2)
        g_off[i] += base;
    if (bid == NBLK - 1 && t == 0)
        g_off[NROWS2] = base + g_bsum[NBLK - 1];       // grand total sentinel
}

// ---------------------------------------------------------------------------
// Scatter over BOTH relations -- ATOMIC-FREE: slot = g_off[row] + rank[e].
// Pure bandwidth pass (reads rows/cols/vals/rank, L2-gathers g_off, writes
// g_edge). Replaces the 27.6 us ATOMG-latency-bound version.
// ---------------------------------------------------------------------------
__global__ void __launch_bounds__(256)
scatter4_kernel(const int* __restrict__ r1, const int* __restrict__ c1,
                const float* __restrict__ v1,
                const int* __restrict__ r2, const int* __restrict__ c2,
                const float* __restrict__ v2,
                int E1, int E2)
{
    const int V1 = (E1 + 3) >> 2;
    const int V2 = (E2 + 3) >> 2;
    int v = blockIdx.x * blockDim.x + threadIdx.x;
    const int* rows; const int* cols; const float* vals; const int* rank;
    int E, rowbase;
    if (v < V1)           { rows = r1; cols = c1; vals = v1; rank = g_rank1; E = E1; rowbase = 0; }
    else if (v < V1 + V2) { rows = r2; cols = c2; vals = v2; rank = g_rank2; E = E2; rowbase = N_NODES; v -= V1; }
    else return;

    const int i = v * 4;
    if (i + 3 < E) {
        const int4   r = __ldg(reinterpret_cast<const int4*>(rows) + v);
        const int4   c = __ldg(reinterpret_cast<const int4*>(cols) + v);
        const float4 w = __ldg(reinterpret_cast<const float4*>(vals) + v);
        const int4   k = *(reinterpret_cast<const int4*>(rank) + v);
        const int p0 = __ldg(&g_off[rowbase + r.x]) + k.x;
        const int p1 = __ldg(&g_off[rowbase + r.y]) + k.y;
        const int p2 = __ldg(&g_off[rowbase + r.z]) + k.z;
        const int p3 = __ldg(&g_off[rowbase + r.w]) + k.w;
        g_edge[p0] = make_int2(c.x, __float_as_int(w.x));
        g_edge[p1] = make_int2(c.y, __float_as_int(w.y));
        g_edge[p2] = make_int2(c.z, __float_as_int(w.z));
        g_edge[p3] = make_int2(c.w, __float_as_int(w.w));
    } else {
        for (int e = i; e < E; ++e) {
            const int p = __ldg(&g_off[rowbase + __ldg(rows + e)]) + rank[e];
            g_edge[p] = make_int2(__ldg(cols + e), __float_as_int(__ldg(vals + e)));
        }
    }
}

// ---------------------------------------------------------------------------
// Dense projection on tensor cores (proven 41.6 us form, unchanged).
// ---------------------------------------------------------------------------
__global__ void __launch_bounds__(256)
gemm_tf32_kernel(const float* __restrict__ in,
                 const float* __restrict__ W1,
                 const float* __restrict__ W2)
{
    __shared__ uint32_t shA[64 * A_PAD];

    const int tid  = threadIdx.x;
    const int warp = tid >> 5;
    const int lane = tid & 31;
    const float* __restrict__ W    = blockIdx.y ? W2   : W1;
    float*       __restrict__ xout = blockIdx.y ? g_x2 : g_x1;

    const int col0 = warp * 16;
    uint32_t Bf[2][16][2];
    #pragma unroll
    for (int nt = 0; nt < 2; ++nt) {
        const int n = col0 + nt * 8 + (lane >> 2);
        #pragma unroll
        for (int kk = 0; kk < 16; ++kk) {
            const int k = kk * 8 + (lane & 3);
            Bf[nt][kk][0] = f2tf32(__ldg(W + k * DIM + n));
            Bf[nt][kk][1] = f2tf32(__ldg(W + (k + 4) * DIM + n));
        }
    }

    #pragma unroll
    for (int t = 0; t < 2; ++t) {
        const int row0 = blockIdx.x * 128 + t * 64;

        #pragma unroll
        for (int i = 0; i < 8; ++i) {
            int idx = tid + i * 256;
            int r   = idx >> 5;
            int c4  = idx & 31;
            float4 v = make_float4(0.f, 0.f, 0.f, 0.f);
            if (row0 + r < N_NODES)
                v = __ldg(reinterpret_cast<const float4*>(in + (size_t)(row0 + r) * DIM) + c4);
            uint32_t* s = shA + r * A_PAD + c4 * 4;
            s[0] = f2tf32(v.x); s[1] = f2tf32(v.y);
            s[2] = f2tf32(v.z); s[3] = f2tf32(v.w);
        }
        __syncthreads();

        #pragma unroll
        for (int rt = 0; rt < 4; ++rt) {
            float acc[2][4] = {};
            const uint32_t* sA = shA + (rt * 16) * A_PAD;
            #pragma unroll
            for (int kk = 0; kk < 16; ++kk) {
                const int r = lane >> 2, c = kk * 8 + (lane & 3);
                uint32_t a0 = sA[r * A_PAD + c];
                uint32_t a1 = sA[(r + 8) * A_PAD + c];
                uint32_t a2 = sA[r * A_PAD + c + 4];
                uint32_t a3 = sA[(r + 8) * A_PAD + c + 4];
                #pragma unroll
                for (int nt = 0; nt < 2; ++nt) {
                    asm volatile(
                        "mma.sync.aligned.m16n8k8.row.col.f32.tf32.tf32.f32 "
                        "{%0,%1,%2,%3}, {%4,%5,%6,%7}, {%8,%9}, {%0,%1,%2,%3};"
                        : "+f"(acc[nt][0]), "+f"(acc[nt][1]),
                          "+f"(acc[nt][2]), "+f"(acc[nt][3])
                        : "r"(a0), "r"(a1), "r"(a2), "r"(a3),
                          "r"(Bf[nt][kk][0]), "r"(Bf[nt][kk][1]));
                }
            }
            const int rowa = row0 + rt * 16 + (lane >> 2);
            const int rowb = rowa + 8;
            #pragma unroll
            for (int nt = 0; nt < 2; ++nt) {
                const int c = col0 + nt * 8 + 2 * (lane & 3);
                if (rowa < N_NODES)
                    *reinterpret_cast<float2*>(xout + (size_t)rowa * DIM + c) =
                        make_float2(acc[nt][0], acc[nt][1]);
                if (rowb < N_NODES)
                    *reinterpret_cast<float2*>(xout + (size_t)rowb * DIM + c) =
                        make_float2(acc[nt][2], acc[nt][3]);
            }
        }
        __syncthreads();   // shA reused by next tile
    }
}

// ---------------------------------------------------------------------------
// Segmented SpMM, warp-cooperative (unchanged: 62 us, at LTS gather floor).
// Also restores the g_cnt == 0 invariant.
// ---------------------------------------------------------------------------
__device__ __forceinline__ void row_accum(const float* __restrict__ x,
                                          int s, int e, int lane,
                                          int* __restrict__ shc,
                                          int* __restrict__ shv,
                                          float4& acc)
{
    for (int i = s; i < e; i += 32) {
        const int idx = i + lane;
        if (idx < e) {
            const int2 t = __ldg(&g_edge[idx]);
            shc[lane] = t.x;
            shv[lane] = t.y;
        }
        __syncwarp();
        const int m = min(e - i, 32);
        int j = 0;
        for (; j + 4 <= m; j += 4) {
            const int c0 = shc[j],     c1 = shc[j + 1];
            const int c2 = shc[j + 2], c3 = shc[j + 3];
            const float4 x0 = __ldg(reinterpret_cast<const float4*>(x + (size_t)c0 * DIM) + lane);
            const float4 x1 = __ldg(reinterpret_cast<const float4*>(x + (size_t)c1 * DIM) + lane);
            const float4 x2 = __ldg(reinterpret_cast<const float4*>(x + (size_t)c2 * DIM) + lane);
            const float4 x3 = __ldg(reinterpret_cast<const float4*>(x + (size_t)c3 * DIM) + lane);
            const float v0 = __int_as_float(shv[j]);
            const float v1 = __int_as_float(shv[j + 1]);
            const float v2 = __int_as_float(shv[j + 2]);
            const float v3 = __int_as_float(shv[j + 3]);
            acc.x = fmaf(v0, x0.x, acc.x); acc.y = fmaf(v0, x0.y, acc.y);
            acc.z = fmaf(v0, x0.z, acc.z); acc.w = fmaf(v0, x0.w, acc.w);
            acc.x = fmaf(v1, x1.x, acc.x); acc.y = fmaf(v1, x1.y, acc.y);
            acc.z = fmaf(v1, x1.z, acc.z); acc.w = fmaf(v1, x1.w, acc.w);
            acc.x = fmaf(v2, x2.x, acc.x); acc.y = fmaf(v2, x2.y, acc.y);
            acc.z = fmaf(v2, x2.z, acc.z); acc.w = fmaf(v2, x2.w, acc.w);
            acc.x = fmaf(v3, x3.x, acc.x); acc.y = fmaf(v3, x3.y, acc.y);
            acc.z = fmaf(v3, x3.z, acc.z); acc.w = fmaf(v3, x3.w, acc.w);
        }
        for (; j < m; ++j) {
            const int   c  = shc[j];
            const float v  = __int_as_float(shv[j]);
            const float4 xv = __ldg(reinterpret_cast<const float4*>(x + (size_t)c * DIM) + lane);
            acc.x = fmaf(v, xv.x, acc.x); acc.y = fmaf(v, xv.y, acc.y);
            acc.z = fmaf(v, xv.z, acc.z); acc.w = fmaf(v, xv.w, acc.w);
        }
        __syncwarp();
    }
}

__global__ void __launch_bounds__(256)
spmm_csr_kernel(float* __restrict__ out)
{
    __shared__ int shc[8][32];
    __shared__ int shv[8][32];

    const int warp = threadIdx.x >> 5;
    const int lane = threadIdx.x & 31;
    const int row  = blockIdx.x * 8 + warp;

    // Restore g_cnt == 0 invariant for the next call (not read here).
    if (warp == 0 && lane < 16) {
        const int z = blockIdx.x * 16 + lane;
        if (z < NROWS2) g_cnt[z] = 0;
    }

    if (row >= N_NODES) return;

    float4 acc = make_float4(0.f, 0.f, 0.f, 0.f);

    row_accum(g_x1, g_off[row],           g_off[row + 1],
              lane, shc[warp], shv[warp], acc);
    row_accum(g_x2, g_off[N_NODES + row], g_off[N_NODES + row + 1],
              lane, shc[warp], shv[warp], acc);

    acc.x = fmaxf(acc.x, 0.f); acc.y = fmaxf(acc.y, 0.f);
    acc.z = fmaxf(acc.z, 0.f); acc.w = fmaxf(acc.w, 0.f);
    reinterpret_cast<float4*>(out + (size_t)row * DIM)[lane] = acc;
}

// ---------------------------------------------------------------------------
// Entry point. Fork-join stream capture: GEMM on a side stream in parallel
// with the (now shorter) CSR build chain; SpMM joins both branches.
// Stream/events are created once (host-side, idempotent, no device memory).
//
// Inputs (metadata order):
//   0 inputs[N,128] f32 | 1 adj1_rows i32 | 2 adj1_cols i32 | 3 adj1_vals f32
//   4 adj2_rows i32 | 5 adj2_cols i32 | 6 adj2_vals f32
//   7 weights_1[128,128] f32 | 8 weights_2[128,128] f32
// Output: [N,128] f32.
// ---------------------------------------------------------------------------
static cudaStream_t s_side   = nullptr;
static cudaEvent_t  s_evFork = nullptr;
static cudaEvent_t  s_evJoin = nullptr;

extern "C" void kernel_launch(void* const* d_in, const int* in_sizes, int n_in,
                              void* d_out, int out_size)
{
    if (s_side == nullptr) {                   // one-time host resource init
        cudaStreamCreateWithFlags(&s_side, cudaStreamNonBlocking);
        cudaEventCreateWithFlags(&s_evFork, cudaEventDisableTiming);
        cudaEventCreateWithFlags(&s_evJoin, cudaEventDisableTiming);
    }

    const float* in  = (const float*)d_in[0];
    const int*   a1r = (const int*)  d_in[1];
    const int*   a1c = (const int*)  d_in[2];
    const float* a1v = (const float*)d_in[3];
    const int*   a2r = (const int*)  d_in[4];
    const int*   a2c = (const int*)  d_in[5];
    const float* a2v = (const float*)d_in[6];
    const float* W1  = (const float*)d_in[7];
    const float* W2  = (const float*)d_in[8];
    float*       out = (float*)d_out;

    const int E1 = in_sizes[1];
    const int E2 = in_sizes[4];

    const int Vtot = (E1 + 3) / 4 + (E2 + 3) / 4;
    const int eblk = (Vtot + 255) / 256;

    // ---- fork: GEMM branch on side stream ---------------------------------
    cudaEventRecord(s_evFork, 0);              // origin = capture (legacy) stream
    cudaStreamWaitEvent(s_side, s_evFork, 0);

    dim3 ggrid((N_NODES + 127) / 128, 2);
    gemm_tf32_kernel<<<ggrid, 256, 0, s_side>>>(in, W1, W2);
    cudaEventRecord(s_evJoin, s_side);

    // ---- main branch: CSR build chain (rank-recording, atomic-free scatter)
    hist4_kernel<<<eblk, 256>>>(a1r, a2r, E1, E2);
    scanA_kernel<<<NBLK, SCAN_B>>>();
    scanBC_kernel<<<NBLK, SCAN_B>>>();
    scatter4_kernel<<<eblk, 256>>>(a1r, a1c, a1v, a2r, a2c, a2v, E1, E2);

    // ---- join: SpMM needs both g_edge (build) and g_x1/g_x2 (GEMM) --------
    cudaStreamWaitEvent(0, s_evJoin, 0);
    spmm_csr_kernel<<<(N_NODES + 7) / 8, 256>>>(out);
}